// round 14
// baseline (speedup 1.0000x reference)
#include <cuda_runtime.h>
#include <cuda_fp16.h>
#include <cstdint>

// ---------------------------------------------------------------------------
// Problem constants
// ---------------------------------------------------------------------------
#define IN_F    784
#define OUT_F   1024
#define BATCH   128
#define NITERS  500
#define GPC     2        // noise iterations per CTA
#define NT      64       // out-feature tile per CTA
#define KC      32       // K chunk
#define NCHUNK  25       // ceil(784/32)
#define NTHREADS 256     // 8 warps: 4 (M) x 2 (N)
#define XPITCH  800      // padded fp16 x row, zeros past 784

#define AP 40            // A smem pitch (halves): 80B rows, conflict-free ldmatrix
#define NP 72            // B smem pitch (halves): 144B rows, conflict-free ldmatrix.trans
#define A_SZH (BATCH * AP)   // 5120 halves per A stage (x3 stages)
#define B_SZH (KC * NP)      // 2304 halves per (stage, g)  (x2 stages x GPC)
#define SMEM_BYTES ((3 * A_SZH + 2 * GPC * B_SZH) * 2)   // 49152 B

#define KSPLIT 7
#define KSEG   112

// ---------------------------------------------------------------------------
// Device scratch
// ---------------------------------------------------------------------------
__device__ __half g_xh[BATCH * XPITCH];
__device__ float  g_np[KSPLIT][OUT_F];
__device__ float  g_ci[OUT_F];
__device__ float  g_dp[KSPLIT][BATCH * OUT_F];
__device__ float  g_invden[BATCH * OUT_F];

// ---------------------------------------------------------------------------
// Helpers
// ---------------------------------------------------------------------------
__device__ __forceinline__ uint32_t smem_u32(const void* p) {
    uint32_t a;
    asm("{ .reg .u64 t; cvta.to.shared.u64 t, %1; cvt.u32.u64 %0, t; }"
        : "=r"(a) : "l"(p));
    return a;
}

__device__ __forceinline__ void mma_f16(float* d, const uint32_t* a,
                                        uint32_t b0, uint32_t b1) {
    asm("mma.sync.aligned.m16n8k16.row.col.f32.f16.f16.f32 "
        "{%0,%1,%2,%3}, {%4,%5,%6,%7}, {%8,%9}, {%0,%1,%2,%3};"
        : "+f"(d[0]), "+f"(d[1]), "+f"(d[2]), "+f"(d[3])
        : "r"(a[0]), "r"(a[1]), "r"(a[2]), "r"(a[3]), "r"(b0), "r"(b1));
}

#define LDMATRIX_X4(r, addr)                                                   \
    asm volatile("ldmatrix.sync.aligned.m8n8.x4.shared.b16 {%0,%1,%2,%3}, [%4];"\
        : "=r"((r)[0]), "=r"((r)[1]), "=r"((r)[2]), "=r"((r)[3]) : "r"(addr))

#define LDMATRIX_X4_T(r, addr)                                                 \
    asm volatile("ldmatrix.sync.aligned.m8n8.x4.trans.shared.b16 {%0,%1,%2,%3}, [%4];"\
        : "=r"((r)[0]), "=r"((r)[1]), "=r"((r)[2]), "=r"((r)[3]) : "r"(addr))

#define CP_ASYNC16(dst, src)                                                   \
    asm volatile("cp.async.cg.shared.global [%0], [%1], 16;"                   \
                 :: "r"(dst), "l"(src) : "memory")
#define CP_COMMIT()  asm volatile("cp.async.commit_group;" ::: "memory")
#define CP_WAIT0()   asm volatile("cp.async.wait_group 0;" ::: "memory")
#define CP_WAIT1()   asm volatile("cp.async.wait_group 1;" ::: "memory")

// ---------------------------------------------------------------------------
// Precompute 0: x -> fp16, padded rows
// ---------------------------------------------------------------------------
__global__ void xh_kernel(const float* __restrict__ x) {
    int i = blockIdx.x * 256 + threadIdx.x;
    int row = i / (XPITCH / 4);
    int c4  = (i % (XPITCH / 4)) * 4;
    float4 v = make_float4(0.f, 0.f, 0.f, 0.f);
    if (c4 < IN_F)
        v = *reinterpret_cast<const float4*>(x + (size_t)row * IN_F + c4);
    __half2 h0 = __floats2half2_rn(v.x, v.y);
    __half2 h1 = __floats2half2_rn(v.z, v.w);
    uint2 u;
    u.x = reinterpret_cast<uint32_t&>(h0);
    u.y = reinterpret_cast<uint32_t&>(h1);
    *reinterpret_cast<uint2*>(&g_xh[(size_t)row * XPITCH + c4]) = u;
}

// ---------------------------------------------------------------------------
// Precompute 1: split-K column norms -> ci = 1/||col||
// ---------------------------------------------------------------------------
__global__ void wnorm_part_kernel(const float* __restrict__ W) {
    int o  = blockIdx.x * 128 + threadIdx.x;
    int k0 = blockIdx.y * KSEG;
    float s = 0.0f;
    #pragma unroll 8
    for (int kk = 0; kk < KSEG; ++kk) {
        float w = W[(size_t)(k0 + kk) * OUT_F + o];
        s = fmaf(w, w, s);
    }
    g_np[blockIdx.y][o] = s;
}

__global__ void colinv_kernel() {
    int o = blockIdx.x * 256 + threadIdx.x;
    float s = 0.0f;
    #pragma unroll
    for (int j = 0; j < KSPLIT; ++j) s += g_np[j][o];
    g_ci[o] = rsqrtf(s);
}

// ---------------------------------------------------------------------------
// Precompute 2: split-K denom^2 -> invden
// ---------------------------------------------------------------------------
__global__ void invden_part_kernel(const float* __restrict__ W,
                                   const float* __restrict__ xg) {
    __shared__ float x2[4][KSEG];
    int o  = blockIdx.x * 256 + threadIdx.x;
    int b0 = blockIdx.y * 4;
    int k0 = blockIdx.z * KSEG;
    for (int i = threadIdx.x; i < 4 * KSEG; i += 256) {
        int bi = i / KSEG, kk = i % KSEG;
        float v = xg[(size_t)(b0 + bi) * IN_F + k0 + kk];
        x2[bi][kk] = v * v;
    }
    __syncthreads();
    float ci  = g_ci[o];
    float ci2 = ci * ci;
    float a0 = 0.f, a1 = 0.f, a2 = 0.f, a3 = 0.f;
    #pragma unroll 4
    for (int kk = 0; kk < KSEG; ++kk) {
        float w  = W[(size_t)(k0 + kk) * OUT_F + o];
        float w2 = w * w * ci2;
        a0 = fmaf(x2[0][kk], w2, a0);
        a1 = fmaf(x2[1][kk], w2, a1);
        a2 = fmaf(x2[2][kk], w2, a2);
        a3 = fmaf(x2[3][kk], w2, a3);
    }
    float* dp = g_dp[blockIdx.z];
    dp[(size_t)(b0 + 0) * OUT_F + o] = a0;
    dp[(size_t)(b0 + 1) * OUT_F + o] = a1;
    dp[(size_t)(b0 + 2) * OUT_F + o] = a2;
    dp[(size_t)(b0 + 3) * OUT_F + o] = a3;
}

__global__ void invden_fin_kernel() {
    int i = blockIdx.x * 256 + threadIdx.x;
    float s = 0.0f;
    #pragma unroll
    for (int j = 0; j < KSPLIT; ++j) s += g_dp[j][i];
    g_invden[i] = rsqrtf(s);
}

// ---------------------------------------------------------------------------
// Main kernel: 256 threads, 2 CTAs/SM, one barrier per K chunk.
// D[g] = x @ (W*ci*(noise_g-1)) via fp16 m16n8k16; out = D * invden.
// ---------------------------------------------------------------------------
__global__ void __launch_bounds__(NTHREADS, 2)
noisy_mma_kernel(const float* __restrict__ W,
                 const float* __restrict__ noise,
                 float* __restrict__ out) {
    extern __shared__ char smch[];
    const uint32_t smb = smem_u32(smch);

    const int tid = threadIdx.x;
    const int l   = tid & 31;
    const int wid = tid >> 5;          // 0..7
    const int rm  = (wid & 3) * 32;    // warp M base (4 M-warps)
    const int cn  = (wid >> 2) * 32;   // warp N base (2 N-warps)

    const int ot     = blockIdx.x & 15;   // 16 o-tiles of 64
    const int nb_grp = blockIdx.x >> 4;   // 250 iter groups
    const int o0     = ot * NT;
    const int n_base = nb_grp * GPC;

    // ldmatrix lane offsets (bytes from smem base)
    const uint32_t a_ld_off =
        ((uint32_t)((rm + ((l >> 3) & 1) * 8 + (l & 7)) * AP + ((l >> 4) & 1) * 8)) * 2;
    const uint32_t b_ld_off =
        ((uint32_t)(((l & 7) + ((l >> 3) & 1) * 8) * NP + cn + ((l >> 4) & 1) * 8)) * 2;

    // producer role: B tiles. 256 threads cover 32k x 16 n-quads (64 cols).
    const int b_k  = tid >> 4;         // 0..15 -> k = k0 + b_k + it*16
    const int b_nq = tid & 15;         // n = b_nq*4
    const float4 civ = *reinterpret_cast<const float4*>(g_ci + o0 + b_nq * 4);

    // producer role: A tile (cp.async). 512 16B tasks over 256 threads.
    const int a_row0 = tid >> 2;             // tasks 0..255
    const int a_qu0  = tid & 3;
    const int a_row1 = (tid + 256) >> 2;     // tasks 256..511
    const int a_qu1  = a_qu0;

    float acc[GPC][2][4][4];
    #pragma unroll
    for (int g = 0; g < GPC; ++g)
        #pragma unroll
        for (int mb = 0; mb < 2; ++mb)
            #pragma unroll
            for (int nb = 0; nb < 4; ++nb)
                #pragma unroll
                for (int r = 0; r < 4; ++r) acc[g][mb][nb][r] = 0.0f;

    auto issueA = [&](int chunk, int sa) {
        const __half* src0 = g_xh + (size_t)a_row0 * XPITCH + chunk * KC + a_qu0 * 8;
        const __half* src1 = g_xh + (size_t)a_row1 * XPITCH + chunk * KC + a_qu1 * 8;
        uint32_t base = smb + (uint32_t)sa * (A_SZH * 2);
        CP_ASYNC16(base + (uint32_t)(a_row0 * AP + a_qu0 * 8) * 2, (const void*)src0);
        CP_ASYNC16(base + (uint32_t)(a_row1 * AP + a_qu1 * 8) * 2, (const void*)src1);
        CP_COMMIT();
    };

    // fused: LDG noise/W -> fma -> cvt -> STS (B stage sb)
    auto loadstoreB = [&](int chunk, int sb) {
        const int k0 = chunk * KC;
        #pragma unroll
        for (int it = 0; it < 2; ++it) {
            const int k = k0 + b_k + it * 16;
            float4 w = make_float4(0.f, 0.f, 0.f, 0.f);
            if (k < IN_F) {
                float4 wr = *reinterpret_cast<const float4*>(
                    W + (size_t)k * OUT_F + o0 + b_nq * 4);
                w.x = wr.x * civ.x; w.y = wr.y * civ.y;
                w.z = wr.z * civ.z; w.w = wr.w * civ.w;
            }
            const int kloc = b_k + it * 16;
            #pragma unroll
            for (int g = 0; g < GPC; ++g) {
                float4 n = make_float4(1.f, 1.f, 1.f, 1.f);
                if (k < IN_F)
                    n = __ldcs(reinterpret_cast<const float4*>(
                        noise + ((size_t)(n_base + g) * IN_F + k) * OUT_F +
                        o0 + b_nq * 4));
                __half2 h0 = __floats2half2_rn(fmaf(n.x, w.x, -w.x),
                                               fmaf(n.y, w.y, -w.y));
                __half2 h1 = __floats2half2_rn(fmaf(n.z, w.z, -w.z),
                                               fmaf(n.w, w.w, -w.w));
                uint2 u;
                u.x = reinterpret_cast<uint32_t&>(h0);
                u.y = reinterpret_cast<uint32_t&>(h1);
                uint32_t off = (uint32_t)(3 * A_SZH + (sb * GPC + g) * B_SZH) * 2 +
                               (uint32_t)(kloc * NP + b_nq * 4) * 2;
                *reinterpret_cast<uint2*>(smch + off) = u;
            }
        }
    };

    auto consume = [&](int sa, int sb) {
        const uint32_t aBase = smb + (uint32_t)sa * (A_SZH * 2) + a_ld_off;
        #pragma unroll
        for (int kstep = 0; kstep < 2; ++kstep) {
            uint32_t a[2][4];
            #pragma unroll
            for (int mb = 0; mb < 2; ++mb)
                LDMATRIX_X4(a[mb], aBase + (uint32_t)(mb * 16 * AP * 2 + kstep * 32));
            #pragma unroll
            for (int g = 0; g < GPC; ++g) {
                const uint32_t bBase = smb +
                    (uint32_t)(3 * A_SZH + (sb * GPC + g) * B_SZH) * 2 +
                    b_ld_off + (uint32_t)(kstep * 16 * NP * 2);
                #pragma unroll
                for (int p = 0; p < 2; ++p) {
                    uint32_t bb[4];
                    LDMATRIX_X4_T(bb, bBase + (uint32_t)(p * 32));
                    mma_f16(acc[g][0][2 * p],     a[0], bb[0], bb[1]);
                    mma_f16(acc[g][1][2 * p],     a[1], bb[0], bb[1]);
                    mma_f16(acc[g][0][2 * p + 1], a[0], bb[2], bb[3]);
                    mma_f16(acc[g][1][2 * p + 1], a[1], bb[2], bb[3]);
                }
            }
        }
    };

    // prologue: A stages 0,1 in flight
    issueA(0, 0);
    issueA(1, 1);

    // one __syncthreads per chunk; A triple-buffered, B double-buffered
    for (int chunk = 0; chunk < NCHUNK; ++chunk) {
        const int sb = chunk & 1;
        const int sa = chunk % 3;
        loadstoreB(chunk, sb);
        if (chunk == NCHUNK - 1) { CP_WAIT0(); } else { CP_WAIT1(); }
        __syncthreads();
        if (chunk + 2 < NCHUNK) issueA(chunk + 2, (chunk + 2) % 3);
        consume(sa, sb);
    }

    // ---- epilogue: scale by invden, store ----
    const int gID = l >> 2;
    const int c   = l & 3;
    #pragma unroll
    for (int mb = 0; mb < 2; ++mb) {
        #pragma unroll
        for (int nb = 0; nb < 4; ++nb) {
            const int b = rm + mb * 16 + gID;
            const int o = o0 + cn + nb * 8 + c * 2;
            const float2 d0 = *reinterpret_cast<const float2*>(
                g_invden + (size_t)b * OUT_F + o);
            const float2 d1 = *reinterpret_cast<const float2*>(
                g_invden + (size_t)(b + 8) * OUT_F + o);
            #pragma unroll
            for (int g = 0; g < GPC; ++g) {
                float2 r0, r1;
                r0.x = acc[g][mb][nb][0] * d0.x;
                r0.y = acc[g][mb][nb][1] * d0.y;
                r1.x = acc[g][mb][nb][2] * d1.x;
                r1.y = acc[g][mb][nb][3] * d1.y;
                float* op = out + ((size_t)(n_base + g) * BATCH + b) * OUT_F + o;
                __stcs(reinterpret_cast<float2*>(op), r0);
                __stcs(reinterpret_cast<float2*>(op + 8 * OUT_F), r1);
            }
        }
    }
}

// ---------------------------------------------------------------------------
// Launch
// ---------------------------------------------------------------------------
extern "C" void kernel_launch(void* const* d_in, const int* in_sizes, int n_in,
                              void* d_out, int out_size) {
    const float* x = nullptr;
    const float* W = nullptr;
    const float* noise = nullptr;
    for (int i = 0; i < n_in; ++i) {
        if (in_sizes[i] == BATCH * IN_F)       x = (const float*)d_in[i];
        else if (in_sizes[i] == IN_F * OUT_F)  W = (const float*)d_in[i];
        else                                   noise = (const float*)d_in[i];
    }
    float* out = (float*)d_out;
    (void)out_size;

    cudaFuncSetAttribute(noisy_mma_kernel,
                         cudaFuncAttributeMaxDynamicSharedMemorySize, SMEM_BYTES);

    xh_kernel<<<(BATCH * XPITCH / 4) / 256, 256>>>(x);
    wnorm_part_kernel<<<dim3(OUT_F / 128, KSPLIT), 128>>>(W);
    colinv_kernel<<<OUT_F / 256, 256>>>();
    invden_part_kernel<<<dim3(OUT_F / 256, BATCH / 4, KSPLIT), 256>>>(W, x);
    invden_fin_kernel<<<BATCH * OUT_F / 256, 256>>>();
    noisy_mma_kernel<<<(OUT_F / NT) * (NITERS / GPC), NTHREADS, SMEM_BYTES>>>(
        W, noise, out);
}

// round 15
// speedup vs baseline: 1.0124x; 1.0124x over previous
#include <cuda_runtime.h>
#include <cuda_fp16.h>
#include <cstdint>

// ---------------------------------------------------------------------------
// Problem constants
// ---------------------------------------------------------------------------
#define IN_F    784
#define OUT_F   1024
#define BATCH   128
#define NITERS  500
#define GPC     2        // noise iterations per CTA
#define NT      64       // out-feature tile per CTA
#define KC      32       // K chunk
#define NCHUNK  25       // ceil(784/32)
#define NTHREADS 256     // 8 warps: 4 (M) x 2 (N)
#define XPITCH  800      // padded fp16 x row, zeros past 784

#define AP 40            // A smem pitch (halves): 80B rows, conflict-free ldmatrix
#define NP 72            // B smem pitch (halves): 144B rows, conflict-free ldmatrix.trans
#define A_SZH (BATCH * AP)   // 5120 halves per A stage (x3 stages)
#define B_SZH (KC * NP)      // 2304 halves per (stage, g)  (x2 stages x GPC)
#define SMEM_BYTES ((3 * A_SZH + 2 * GPC * B_SZH) * 2)   // 49152 B

#define KSPLIT 7
#define KSEG   112

// ---------------------------------------------------------------------------
// Device scratch
// ---------------------------------------------------------------------------
__device__ __half g_xh[BATCH * XPITCH];
__device__ float  g_np[KSPLIT][OUT_F];
__device__ float  g_ci[OUT_F];
__device__ float  g_dp[KSPLIT][BATCH * OUT_F];
__device__ float  g_invden[BATCH * OUT_F];

// ---------------------------------------------------------------------------
// Helpers
// ---------------------------------------------------------------------------
__device__ __forceinline__ uint32_t smem_u32(const void* p) {
    uint32_t a;
    asm("{ .reg .u64 t; cvta.to.shared.u64 t, %1; cvt.u32.u64 %0, t; }"
        : "=r"(a) : "l"(p));
    return a;
}

__device__ __forceinline__ void mma_f16(float* d, const uint32_t* a,
                                        uint32_t b0, uint32_t b1) {
    asm("mma.sync.aligned.m16n8k16.row.col.f32.f16.f16.f32 "
        "{%0,%1,%2,%3}, {%4,%5,%6,%7}, {%8,%9}, {%0,%1,%2,%3};"
        : "+f"(d[0]), "+f"(d[1]), "+f"(d[2]), "+f"(d[3])
        : "r"(a[0]), "r"(a[1]), "r"(a[2]), "r"(a[3]), "r"(b0), "r"(b1));
}

#define LDMATRIX_X4(r, addr)                                                   \
    asm volatile("ldmatrix.sync.aligned.m8n8.x4.shared.b16 {%0,%1,%2,%3}, [%4];"\
        : "=r"((r)[0]), "=r"((r)[1]), "=r"((r)[2]), "=r"((r)[3]) : "r"(addr))

#define LDMATRIX_X4_T(r, addr)                                                 \
    asm volatile("ldmatrix.sync.aligned.m8n8.x4.trans.shared.b16 {%0,%1,%2,%3}, [%4];"\
        : "=r"((r)[0]), "=r"((r)[1]), "=r"((r)[2]), "=r"((r)[3]) : "r"(addr))

#define CP_ASYNC16(dst, src)                                                   \
    asm volatile("cp.async.cg.shared.global [%0], [%1], 16;"                   \
                 :: "r"(dst), "l"(src) : "memory")
#define CP_COMMIT()  asm volatile("cp.async.commit_group;" ::: "memory")
#define CP_WAIT0()   asm volatile("cp.async.wait_group 0;" ::: "memory")
#define CP_WAIT1()   asm volatile("cp.async.wait_group 1;" ::: "memory")

// ---------------------------------------------------------------------------
// Precompute 0: x -> fp16, padded rows
// ---------------------------------------------------------------------------
__global__ void xh_kernel(const float* __restrict__ x) {
    int i = blockIdx.x * 256 + threadIdx.x;
    int row = i / (XPITCH / 4);
    int c4  = (i % (XPITCH / 4)) * 4;
    float4 v = make_float4(0.f, 0.f, 0.f, 0.f);
    if (c4 < IN_F)
        v = *reinterpret_cast<const float4*>(x + (size_t)row * IN_F + c4);
    __half2 h0 = __floats2half2_rn(v.x, v.y);
    __half2 h1 = __floats2half2_rn(v.z, v.w);
    uint2 u;
    u.x = reinterpret_cast<uint32_t&>(h0);
    u.y = reinterpret_cast<uint32_t&>(h1);
    *reinterpret_cast<uint2*>(&g_xh[(size_t)row * XPITCH + c4]) = u;
}

// ---------------------------------------------------------------------------
// Precompute 1: split-K column norms -> ci = 1/||col||
// ---------------------------------------------------------------------------
__global__ void wnorm_part_kernel(const float* __restrict__ W) {
    int o  = blockIdx.x * 128 + threadIdx.x;
    int k0 = blockIdx.y * KSEG;
    float s = 0.0f;
    #pragma unroll 8
    for (int kk = 0; kk < KSEG; ++kk) {
        float w = W[(size_t)(k0 + kk) * OUT_F + o];
        s = fmaf(w, w, s);
    }
    g_np[blockIdx.y][o] = s;
}

__global__ void colinv_kernel() {
    int o = blockIdx.x * 256 + threadIdx.x;
    float s = 0.0f;
    #pragma unroll
    for (int j = 0; j < KSPLIT; ++j) s += g_np[j][o];
    g_ci[o] = rsqrtf(s);
}

// ---------------------------------------------------------------------------
// Precompute 2: split-K denom^2 -> invden
// ---------------------------------------------------------------------------
__global__ void invden_part_kernel(const float* __restrict__ W,
                                   const float* __restrict__ xg) {
    __shared__ float x2[4][KSEG];
    int o  = blockIdx.x * 256 + threadIdx.x;
    int b0 = blockIdx.y * 4;
    int k0 = blockIdx.z * KSEG;
    for (int i = threadIdx.x; i < 4 * KSEG; i += 256) {
        int bi = i / KSEG, kk = i % KSEG;
        float v = xg[(size_t)(b0 + bi) * IN_F + k0 + kk];
        x2[bi][kk] = v * v;
    }
    __syncthreads();
    float ci  = g_ci[o];
    float ci2 = ci * ci;
    float a0 = 0.f, a1 = 0.f, a2 = 0.f, a3 = 0.f;
    #pragma unroll 4
    for (int kk = 0; kk < KSEG; ++kk) {
        float w  = W[(size_t)(k0 + kk) * OUT_F + o];
        float w2 = w * w * ci2;
        a0 = fmaf(x2[0][kk], w2, a0);
        a1 = fmaf(x2[1][kk], w2, a1);
        a2 = fmaf(x2[2][kk], w2, a2);
        a3 = fmaf(x2[3][kk], w2, a3);
    }
    float* dp = g_dp[blockIdx.z];
    dp[(size_t)(b0 + 0) * OUT_F + o] = a0;
    dp[(size_t)(b0 + 1) * OUT_F + o] = a1;
    dp[(size_t)(b0 + 2) * OUT_F + o] = a2;
    dp[(size_t)(b0 + 3) * OUT_F + o] = a3;
}

__global__ void invden_fin_kernel() {
    int i = blockIdx.x * 256 + threadIdx.x;
    float s = 0.0f;
    #pragma unroll
    for (int j = 0; j < KSPLIT; ++j) s += g_dp[j][i];
    g_invden[i] = rsqrtf(s);
}

// ---------------------------------------------------------------------------
// Main kernel: 256 threads, 2 CTAs/SM, one barrier per K chunk.
// D[g] = x @ (W*ci*(noise_g-1)) via fp16 m16n8k16; out = D * invden.
// ---------------------------------------------------------------------------
__global__ void __launch_bounds__(NTHREADS, 2)
noisy_mma_kernel(const float* __restrict__ W,
                 const float* __restrict__ noise,
                 float* __restrict__ out) {
    extern __shared__ char smch[];
    const uint32_t smb = smem_u32(smch);

    const int tid = threadIdx.x;
    const int l   = tid & 31;
    const int wid = tid >> 5;          // 0..7
    const int rm  = (wid & 3) * 32;    // warp M base (4 M-warps)
    const int cn  = (wid >> 2) * 32;   // warp N base (2 N-warps)

    const int ot     = blockIdx.x & 15;   // 16 o-tiles of 64
    const int nb_grp = blockIdx.x >> 4;   // 250 iter groups
    const int o0     = ot * NT;
    const int n_base = nb_grp * GPC;

    // ldmatrix lane offsets (bytes from smem base)
    const uint32_t a_ld_off =
        ((uint32_t)((rm + ((l >> 3) & 1) * 8 + (l & 7)) * AP + ((l >> 4) & 1) * 8)) * 2;
    const uint32_t b_ld_off =
        ((uint32_t)(((l & 7) + ((l >> 3) & 1) * 8) * NP + cn + ((l >> 4) & 1) * 8)) * 2;

    // producer role: B tiles. 256 threads cover 32k x 16 n-quads (64 cols).
    const int b_k  = tid >> 4;         // 0..15 -> k = k0 + b_k + it*16
    const int b_nq = tid & 15;         // n = b_nq*4
    const float4 civ = *reinterpret_cast<const float4*>(g_ci + o0 + b_nq * 4);

    // producer role: A tile (cp.async). 512 16B tasks over 256 threads.
    const int a_row0 = tid >> 2;             // tasks 0..255
    const int a_qu0  = tid & 3;
    const int a_row1 = (tid + 256) >> 2;     // tasks 256..511
    const int a_qu1  = a_qu0;

    float acc[GPC][2][4][4];
    #pragma unroll
    for (int g = 0; g < GPC; ++g)
        #pragma unroll
        for (int mb = 0; mb < 2; ++mb)
            #pragma unroll
            for (int nb = 0; nb < 4; ++nb)
                #pragma unroll
                for (int r = 0; r < 4; ++r) acc[g][mb][nb][r] = 0.0f;

    auto issueA = [&](int chunk, int sa) {
        const __half* src0 = g_xh + (size_t)a_row0 * XPITCH + chunk * KC + a_qu0 * 8;
        const __half* src1 = g_xh + (size_t)a_row1 * XPITCH + chunk * KC + a_qu1 * 8;
        uint32_t base = smb + (uint32_t)sa * (A_SZH * 2);
        CP_ASYNC16(base + (uint32_t)(a_row0 * AP + a_qu0 * 8) * 2, (const void*)src0);
        CP_ASYNC16(base + (uint32_t)(a_row1 * AP + a_qu1 * 8) * 2, (const void*)src1);
        CP_COMMIT();
    };

    // fused: LDG noise/W -> fma -> cvt -> STS (B stage sb)
    auto loadstoreB = [&](int chunk, int sb) {
        const int k0 = chunk * KC;
        #pragma unroll
        for (int it = 0; it < 2; ++it) {
            const int k = k0 + b_k + it * 16;
            float4 w = make_float4(0.f, 0.f, 0.f, 0.f);
            if (k < IN_F) {
                float4 wr = *reinterpret_cast<const float4*>(
                    W + (size_t)k * OUT_F + o0 + b_nq * 4);
                w.x = wr.x * civ.x; w.y = wr.y * civ.y;
                w.z = wr.z * civ.z; w.w = wr.w * civ.w;
            }
            const int kloc = b_k + it * 16;
            #pragma unroll
            for (int g = 0; g < GPC; ++g) {
                float4 n = make_float4(1.f, 1.f, 1.f, 1.f);
                if (k < IN_F)
                    n = __ldcs(reinterpret_cast<const float4*>(
                        noise + ((size_t)(n_base + g) * IN_F + k) * OUT_F +
                        o0 + b_nq * 4));
                __half2 h0 = __floats2half2_rn(fmaf(n.x, w.x, -w.x),
                                               fmaf(n.y, w.y, -w.y));
                __half2 h1 = __floats2half2_rn(fmaf(n.z, w.z, -w.z),
                                               fmaf(n.w, w.w, -w.w));
                uint2 u;
                u.x = reinterpret_cast<uint32_t&>(h0);
                u.y = reinterpret_cast<uint32_t&>(h1);
                uint32_t off = (uint32_t)(3 * A_SZH + (sb * GPC + g) * B_SZH) * 2 +
                               (uint32_t)(kloc * NP + b_nq * 4) * 2;
                *reinterpret_cast<uint2*>(smch + off) = u;
            }
        }
    };

    auto consume = [&](int sa, int sb) {
        const uint32_t aBase = smb + (uint32_t)sa * (A_SZH * 2) + a_ld_off;
        #pragma unroll
        for (int kstep = 0; kstep < 2; ++kstep) {
            uint32_t a[2][4];
            #pragma unroll
            for (int mb = 0; mb < 2; ++mb)
                LDMATRIX_X4(a[mb], aBase + (uint32_t)(mb * 16 * AP * 2 + kstep * 32));
            #pragma unroll
            for (int g = 0; g < GPC; ++g) {
                const uint32_t bBase = smb +
                    (uint32_t)(3 * A_SZH + (sb * GPC + g) * B_SZH) * 2 +
                    b_ld_off + (uint32_t)(kstep * 16 * NP * 2);
                #pragma unroll
                for (int p = 0; p < 2; ++p) {
                    uint32_t bb[4];
                    LDMATRIX_X4_T(bb, bBase + (uint32_t)(p * 32));
                    mma_f16(acc[g][0][2 * p],     a[0], bb[0], bb[1]);
                    mma_f16(acc[g][1][2 * p],     a[1], bb[0], bb[1]);
                    mma_f16(acc[g][0][2 * p + 1], a[0], bb[2], bb[3]);
                    mma_f16(acc[g][1][2 * p + 1], a[1], bb[2], bb[3]);
                }
            }
        }
    };

    // prologue: A stages 0,1 in flight
    issueA(0, 0);
    issueA(1, 1);

    // one __syncthreads per chunk; A triple-buffered, B double-buffered
    for (int chunk = 0; chunk < NCHUNK; ++chunk) {
        const int sb = chunk & 1;
        const int sa = chunk % 3;
        loadstoreB(chunk, sb);
        if (chunk == NCHUNK - 1) { CP_WAIT0(); } else { CP_WAIT1(); }
        __syncthreads();
        if (chunk + 2 < NCHUNK) issueA(chunk + 2, (chunk + 2) % 3);
        consume(sa, sb);
    }

    // ---- epilogue: scale by invden, store ----
    const int gID = l >> 2;
    const int c   = l & 3;
    #pragma unroll
    for (int mb = 0; mb < 2; ++mb) {
        #pragma unroll
        for (int nb = 0; nb < 4; ++nb) {
            const int b = rm + mb * 16 + gID;
            const int o = o0 + cn + nb * 8 + c * 2;
            const float2 d0 = *reinterpret_cast<const float2*>(
                g_invden + (size_t)b * OUT_F + o);
            const float2 d1 = *reinterpret_cast<const float2*>(
                g_invden + (size_t)(b + 8) * OUT_F + o);
            #pragma unroll
            for (int g = 0; g < GPC; ++g) {
                float2 r0, r1;
                r0.x = acc[g][mb][nb][0] * d0.x;
                r0.y = acc[g][mb][nb][1] * d0.y;
                r1.x = acc[g][mb][nb][2] * d1.x;
                r1.y = acc[g][mb][nb][3] * d1.y;
                float* op = out + ((size_t)(n_base + g) * BATCH + b) * OUT_F + o;
                __stcs(reinterpret_cast<float2*>(op), r0);
                __stcs(reinterpret_cast<float2*>(op + 8 * OUT_F), r1);
            }
        }
    }
}

// ---------------------------------------------------------------------------
// Launch
// ---------------------------------------------------------------------------
extern "C" void kernel_launch(void* const* d_in, const int* in_sizes, int n_in,
                              void* d_out, int out_size) {
    const float* x = nullptr;
    const float* W = nullptr;
    const float* noise = nullptr;
    for (int i = 0; i < n_in; ++i) {
        if (in_sizes[i] == BATCH * IN_F)       x = (const float*)d_in[i];
        else if (in_sizes[i] == IN_F * OUT_F)  W = (const float*)d_in[i];
        else                                   noise = (const float*)d_in[i];
    }
    float* out = (float*)d_out;
    (void)out_size;

    cudaFuncSetAttribute(noisy_mma_kernel,
                         cudaFuncAttributeMaxDynamicSharedMemorySize, SMEM_BYTES);

    xh_kernel<<<(BATCH * XPITCH / 4) / 256, 256>>>(x);
    wnorm_part_kernel<<<dim3(OUT_F / 128, KSPLIT), 128>>>(W);
    colinv_kernel<<<OUT_F / 256, 256>>>();
    invden_part_kernel<<<dim3(OUT_F / 256, BATCH / 4, KSPLIT), 256>>>(W, x);
    invden_fin_kernel<<<BATCH * OUT_F / 256, 256>>>();
    noisy_mma_kernel<<<(OUT_F / NT) * (NITERS / GPC), NTHREADS, SMEM_BYTES>>>(
        W, noise, out);
}

// round 16
// speedup vs baseline: 1.0135x; 1.0010x over previous
#include <cuda_runtime.h>
#include <cuda_fp16.h>
#include <cstdint>

// ---------------------------------------------------------------------------
// Problem constants
// ---------------------------------------------------------------------------
#define IN_F    784
#define OUT_F   1024
#define BATCH   128
#define NITERS  500
#define GPC     2        // noise iterations per CTA
#define NT      64       // out-feature tile per CTA
#define KC      32       // K chunk
#define NCHUNK  25       // ceil(784/32)
#define NTHREADS 256     // 8 warps: 4 (M) x 2 (N)
#define XPITCH  800      // padded fp16 x row, zeros past 784

#define AP 40            // A smem pitch (halves): 80B rows, conflict-free ldmatrix
#define NP 72            // B smem pitch (halves): 144B rows, conflict-free ldmatrix.trans
#define A_SZH (BATCH * AP)   // 5120 halves per A stage (x3 stages)
#define B_SZH (KC * NP)      // 2304 halves per (stage, g)  (x2 stages x GPC)
#define SMEM_BYTES ((3 * A_SZH + 2 * GPC * B_SZH) * 2)   // 49152 B

#define KSPLIT 7
#define KSEG   112

// ---------------------------------------------------------------------------
// Device scratch
// ---------------------------------------------------------------------------
__device__ __half g_xh[BATCH * XPITCH];
__device__ float  g_np[KSPLIT][OUT_F];
__device__ float  g_ci[OUT_F];
__device__ float  g_dp[KSPLIT][BATCH * OUT_F];
__device__ float  g_invden[BATCH * OUT_F];

// ---------------------------------------------------------------------------
// Helpers
// ---------------------------------------------------------------------------
__device__ __forceinline__ uint32_t smem_u32(const void* p) {
    uint32_t a;
    asm("{ .reg .u64 t; cvta.to.shared.u64 t, %1; cvt.u32.u64 %0, t; }"
        : "=r"(a) : "l"(p));
    return a;
}

__device__ __forceinline__ void mma_f16(float* d, const uint32_t* a,
                                        uint32_t b0, uint32_t b1) {
    asm("mma.sync.aligned.m16n8k16.row.col.f32.f16.f16.f32 "
        "{%0,%1,%2,%3}, {%4,%5,%6,%7}, {%8,%9}, {%0,%1,%2,%3};"
        : "+f"(d[0]), "+f"(d[1]), "+f"(d[2]), "+f"(d[3])
        : "r"(a[0]), "r"(a[1]), "r"(a[2]), "r"(a[3]), "r"(b0), "r"(b1));
}

#define LDMATRIX_X4(r, addr)                                                   \
    asm volatile("ldmatrix.sync.aligned.m8n8.x4.shared.b16 {%0,%1,%2,%3}, [%4];"\
        : "=r"((r)[0]), "=r"((r)[1]), "=r"((r)[2]), "=r"((r)[3]) : "r"(addr))

#define LDMATRIX_X4_T(r, addr)                                                 \
    asm volatile("ldmatrix.sync.aligned.m8n8.x4.trans.shared.b16 {%0,%1,%2,%3}, [%4];"\
        : "=r"((r)[0]), "=r"((r)[1]), "=r"((r)[2]), "=r"((r)[3]) : "r"(addr))

#define CP_ASYNC16(dst, src)                                                   \
    asm volatile("cp.async.cg.shared.global [%0], [%1], 16;"                   \
                 :: "r"(dst), "l"(src) : "memory")
#define CP_COMMIT()  asm volatile("cp.async.commit_group;" ::: "memory")
#define CP_WAIT0()   asm volatile("cp.async.wait_group 0;" ::: "memory")
#define CP_WAIT1()   asm volatile("cp.async.wait_group 1;" ::: "memory")

// ---------------------------------------------------------------------------
// Precompute 0: x -> fp16, padded rows
// ---------------------------------------------------------------------------
__global__ void xh_kernel(const float* __restrict__ x) {
    int i = blockIdx.x * 256 + threadIdx.x;
    int row = i / (XPITCH / 4);
    int c4  = (i % (XPITCH / 4)) * 4;
    float4 v = make_float4(0.f, 0.f, 0.f, 0.f);
    if (c4 < IN_F)
        v = *reinterpret_cast<const float4*>(x + (size_t)row * IN_F + c4);
    __half2 h0 = __floats2half2_rn(v.x, v.y);
    __half2 h1 = __floats2half2_rn(v.z, v.w);
    uint2 u;
    u.x = reinterpret_cast<uint32_t&>(h0);
    u.y = reinterpret_cast<uint32_t&>(h1);
    *reinterpret_cast<uint2*>(&g_xh[(size_t)row * XPITCH + c4]) = u;
}

// ---------------------------------------------------------------------------
// Precompute 1: split-K column norms -> ci = 1/||col||
// ---------------------------------------------------------------------------
__global__ void wnorm_part_kernel(const float* __restrict__ W) {
    int o  = blockIdx.x * 128 + threadIdx.x;
    int k0 = blockIdx.y * KSEG;
    float s = 0.0f;
    #pragma unroll 8
    for (int kk = 0; kk < KSEG; ++kk) {
        float w = W[(size_t)(k0 + kk) * OUT_F + o];
        s = fmaf(w, w, s);
    }
    g_np[blockIdx.y][o] = s;
}

__global__ void colinv_kernel() {
    int o = blockIdx.x * 256 + threadIdx.x;
    float s = 0.0f;
    #pragma unroll
    for (int j = 0; j < KSPLIT; ++j) s += g_np[j][o];
    g_ci[o] = rsqrtf(s);
}

// ---------------------------------------------------------------------------
// Precompute 2: split-K denom^2 -> invden
// ---------------------------------------------------------------------------
__global__ void invden_part_kernel(const float* __restrict__ W,
                                   const float* __restrict__ xg) {
    __shared__ float x2[4][KSEG];
    int o  = blockIdx.x * 256 + threadIdx.x;
    int b0 = blockIdx.y * 4;
    int k0 = blockIdx.z * KSEG;
    for (int i = threadIdx.x; i < 4 * KSEG; i += 256) {
        int bi = i / KSEG, kk = i % KSEG;
        float v = xg[(size_t)(b0 + bi) * IN_F + k0 + kk];
        x2[bi][kk] = v * v;
    }
    __syncthreads();
    float ci  = g_ci[o];
    float ci2 = ci * ci;
    float a0 = 0.f, a1 = 0.f, a2 = 0.f, a3 = 0.f;
    #pragma unroll 4
    for (int kk = 0; kk < KSEG; ++kk) {
        float w  = W[(size_t)(k0 + kk) * OUT_F + o];
        float w2 = w * w * ci2;
        a0 = fmaf(x2[0][kk], w2, a0);
        a1 = fmaf(x2[1][kk], w2, a1);
        a2 = fmaf(x2[2][kk], w2, a2);
        a3 = fmaf(x2[3][kk], w2, a3);
    }
    float* dp = g_dp[blockIdx.z];
    dp[(size_t)(b0 + 0) * OUT_F + o] = a0;
    dp[(size_t)(b0 + 1) * OUT_F + o] = a1;
    dp[(size_t)(b0 + 2) * OUT_F + o] = a2;
    dp[(size_t)(b0 + 3) * OUT_F + o] = a3;
}

__global__ void invden_fin_kernel() {
    int i = blockIdx.x * 256 + threadIdx.x;
    float s = 0.0f;
    #pragma unroll
    for (int j = 0; j < KSPLIT; ++j) s += g_dp[j][i];
    g_invden[i] = rsqrtf(s);
}

// ---------------------------------------------------------------------------
// Main kernel: 256 threads, 2 CTAs/SM, one barrier per K chunk.
// D[g] = x @ (W*ci*(noise_g-1)) via fp16 m16n8k16; out = D * invden.
// ---------------------------------------------------------------------------
__global__ void __launch_bounds__(NTHREADS, 2)
noisy_mma_kernel(const float* __restrict__ W,
                 const float* __restrict__ noise,
                 float* __restrict__ out) {
    extern __shared__ char smch[];
    const uint32_t smb = smem_u32(smch);

    const int tid = threadIdx.x;
    const int l   = tid & 31;
    const int wid = tid >> 5;          // 0..7
    const int rm  = (wid & 3) * 32;    // warp M base (4 M-warps)
    const int cn  = (wid >> 2) * 32;   // warp N base (2 N-warps)

    const int ot     = blockIdx.x & 15;   // 16 o-tiles of 64
    const int nb_grp = blockIdx.x >> 4;   // 250 iter groups
    const int o0     = ot * NT;
    const int n_base = nb_grp * GPC;

    // ldmatrix lane offsets (bytes from smem base)
    const uint32_t a_ld_off =
        ((uint32_t)((rm + ((l >> 3) & 1) * 8 + (l & 7)) * AP + ((l >> 4) & 1) * 8)) * 2;
    const uint32_t b_ld_off =
        ((uint32_t)(((l & 7) + ((l >> 3) & 1) * 8) * NP + cn + ((l >> 4) & 1) * 8)) * 2;

    // producer role: B tiles. 256 threads cover 32k x 16 n-quads (64 cols).
    const int b_k  = tid >> 4;         // 0..15 -> k = k0 + b_k + it*16
    const int b_nq = tid & 15;         // n = b_nq*4
    const float4 civ = *reinterpret_cast<const float4*>(g_ci + o0 + b_nq * 4);

    // producer role: A tile (cp.async). 512 16B tasks over 256 threads.
    const int a_row0 = tid >> 2;             // tasks 0..255
    const int a_qu0  = tid & 3;
    const int a_row1 = (tid + 256) >> 2;     // tasks 256..511
    const int a_qu1  = a_qu0;

    float acc[GPC][2][4][4];
    #pragma unroll
    for (int g = 0; g < GPC; ++g)
        #pragma unroll
        for (int mb = 0; mb < 2; ++mb)
            #pragma unroll
            for (int nb = 0; nb < 4; ++nb)
                #pragma unroll
                for (int r = 0; r < 4; ++r) acc[g][mb][nb][r] = 0.0f;

    auto issueA = [&](int chunk, int sa) {
        const __half* src0 = g_xh + (size_t)a_row0 * XPITCH + chunk * KC + a_qu0 * 8;
        const __half* src1 = g_xh + (size_t)a_row1 * XPITCH + chunk * KC + a_qu1 * 8;
        uint32_t base = smb + (uint32_t)sa * (A_SZH * 2);
        CP_ASYNC16(base + (uint32_t)(a_row0 * AP + a_qu0 * 8) * 2, (const void*)src0);
        CP_ASYNC16(base + (uint32_t)(a_row1 * AP + a_qu1 * 8) * 2, (const void*)src1);
        CP_COMMIT();
    };

    // fused: LDG noise/W -> fma -> cvt -> STS (B stage sb)
    auto loadstoreB = [&](int chunk, int sb) {
        const int k0 = chunk * KC;
        #pragma unroll
        for (int it = 0; it < 2; ++it) {
            const int k = k0 + b_k + it * 16;
            float4 w = make_float4(0.f, 0.f, 0.f, 0.f);
            if (k < IN_F) {
                float4 wr = *reinterpret_cast<const float4*>(
                    W + (size_t)k * OUT_F + o0 + b_nq * 4);
                w.x = wr.x * civ.x; w.y = wr.y * civ.y;
                w.z = wr.z * civ.z; w.w = wr.w * civ.w;
            }
            const int kloc = b_k + it * 16;
            #pragma unroll
            for (int g = 0; g < GPC; ++g) {
                float4 n = make_float4(1.f, 1.f, 1.f, 1.f);
                if (k < IN_F)
                    n = __ldcs(reinterpret_cast<const float4*>(
                        noise + ((size_t)(n_base + g) * IN_F + k) * OUT_F +
                        o0 + b_nq * 4));
                __half2 h0 = __floats2half2_rn(fmaf(n.x, w.x, -w.x),
                                               fmaf(n.y, w.y, -w.y));
                __half2 h1 = __floats2half2_rn(fmaf(n.z, w.z, -w.z),
                                               fmaf(n.w, w.w, -w.w));
                uint2 u;
                u.x = reinterpret_cast<uint32_t&>(h0);
                u.y = reinterpret_cast<uint32_t&>(h1);
                uint32_t off = (uint32_t)(3 * A_SZH + (sb * GPC + g) * B_SZH) * 2 +
                               (uint32_t)(kloc * NP + b_nq * 4) * 2;
                *reinterpret_cast<uint2*>(smch + off) = u;
            }
        }
    };

    auto consume = [&](int sa, int sb) {
        const uint32_t aBase = smb + (uint32_t)sa * (A_SZH * 2) + a_ld_off;
        #pragma unroll
        for (int kstep = 0; kstep < 2; ++kstep) {
            uint32_t a[2][4];
            #pragma unroll
            for (int mb = 0; mb < 2; ++mb)
                LDMATRIX_X4(a[mb], aBase + (uint32_t)(mb * 16 * AP * 2 + kstep * 32));
            #pragma unroll
            for (int g = 0; g < GPC; ++g) {
                const uint32_t bBase = smb +
                    (uint32_t)(3 * A_SZH + (sb * GPC + g) * B_SZH) * 2 +
                    b_ld_off + (uint32_t)(kstep * 16 * NP * 2);
                #pragma unroll
                for (int p = 0; p < 2; ++p) {
                    uint32_t bb[4];
                    LDMATRIX_X4_T(bb, bBase + (uint32_t)(p * 32));
                    mma_f16(acc[g][0][2 * p],     a[0], bb[0], bb[1]);
                    mma_f16(acc[g][1][2 * p],     a[1], bb[0], bb[1]);
                    mma_f16(acc[g][0][2 * p + 1], a[0], bb[2], bb[3]);
                    mma_f16(acc[g][1][2 * p + 1], a[1], bb[2], bb[3]);
                }
            }
        }
    };

    // prologue: A stages 0,1 in flight
    issueA(0, 0);
    issueA(1, 1);

    // one __syncthreads per chunk; A triple-buffered, B double-buffered
    for (int chunk = 0; chunk < NCHUNK; ++chunk) {
        const int sb = chunk & 1;
        const int sa = chunk % 3;
        loadstoreB(chunk, sb);
        if (chunk == NCHUNK - 1) { CP_WAIT0(); } else { CP_WAIT1(); }
        __syncthreads();
        if (chunk + 2 < NCHUNK) issueA(chunk + 2, (chunk + 2) % 3);
        consume(sa, sb);
    }

    // ---- epilogue: scale by invden, store ----
    const int gID = l >> 2;
    const int c   = l & 3;
    #pragma unroll
    for (int mb = 0; mb < 2; ++mb) {
        #pragma unroll
        for (int nb = 0; nb < 4; ++nb) {
            const int b = rm + mb * 16 + gID;
            const int o = o0 + cn + nb * 8 + c * 2;
            const float2 d0 = *reinterpret_cast<const float2*>(
                g_invden + (size_t)b * OUT_F + o);
            const float2 d1 = *reinterpret_cast<const float2*>(
                g_invden + (size_t)(b + 8) * OUT_F + o);
            #pragma unroll
            for (int g = 0; g < GPC; ++g) {
                float2 r0, r1;
                r0.x = acc[g][mb][nb][0] * d0.x;
                r0.y = acc[g][mb][nb][1] * d0.y;
                r1.x = acc[g][mb][nb][2] * d1.x;
                r1.y = acc[g][mb][nb][3] * d1.y;
                float* op = out + ((size_t)(n_base + g) * BATCH + b) * OUT_F + o;
                __stcs(reinterpret_cast<float2*>(op), r0);
                __stcs(reinterpret_cast<float2*>(op + 8 * OUT_F), r1);
            }
        }
    }
}

// ---------------------------------------------------------------------------
// Launch
// ---------------------------------------------------------------------------
extern "C" void kernel_launch(void* const* d_in, const int* in_sizes, int n_in,
                              void* d_out, int out_size) {
    const float* x = nullptr;
    const float* W = nullptr;
    const float* noise = nullptr;
    for (int i = 0; i < n_in; ++i) {
        if (in_sizes[i] == BATCH * IN_F)       x = (const float*)d_in[i];
        else if (in_sizes[i] == IN_F * OUT_F)  W = (const float*)d_in[i];
        else                                   noise = (const float*)d_in[i];
    }
    float* out = (float*)d_out;
    (void)out_size;

    cudaFuncSetAttribute(noisy_mma_kernel,
                         cudaFuncAttributeMaxDynamicSharedMemorySize, SMEM_BYTES);

    xh_kernel<<<(BATCH * XPITCH / 4) / 256, 256>>>(x);
    wnorm_part_kernel<<<dim3(OUT_F / 128, KSPLIT), 128>>>(W);
    colinv_kernel<<<OUT_F / 256, 256>>>();
    invden_part_kernel<<<dim3(OUT_F / 256, BATCH / 4, KSPLIT), 256>>>(W, x);
    invden_fin_kernel<<<BATCH * OUT_F / 256, 256>>>();
    noisy_mma_kernel<<<(OUT_F / NT) * (NITERS / GPC), NTHREADS, SMEM_BYTES>>>(
        W, noise, out);
}